// round 8
// baseline (speedup 1.0000x reference)
#include <cuda_runtime.h>
#include <cuda_bf16.h>

// loss = sum_{pos} softplus(-p)/n_pos + sum_{neg} softplus(p)/n_neg
// over 8192x8192 f32 + i32. Streaming reduction, HBM-bound.
// R8 (= R6/R7 retry after repeated infra failures): R1 loop shape (256thr,
// 2 LDG.128/iter — stays under the L1tex wavefront-queue limit:
// nw*n_LDG*nL = 16*2*4 = 128 < 248), plus the fused last-block final
// reduction (kills the 5.3us stage2 launch).

#define NBLOCKS  1184        // 148 SMs * 8 CTAs
#define NTHREADS 256
#define N_TOTAL  67108864    // 8192*8192
#define N_VEC4   16777216    // N_TOTAL / 4
#define STRIDE   (NBLOCKS * NTHREADS)   // 303104, compile-time

__device__ float g_pos[NBLOCKS];
__device__ float g_neg[NBLOCKS];
__device__ int   g_cnt[NBLOCKS];
__device__ int   g_ticket;   // zero-init; last block resets it each launch

// softplus(x)  = log1p(e^{-|x|}) + max(x, 0)
// softplus(-x) = log1p(e^{-|x|}) + max(-x, 0)
// -> one EX2 + one LG2 per element regardless of label.
__device__ __forceinline__ void lane_accum(float x, int y,
                                           float& pos, float& neg, int& cnt) {
    float ax     = fabsf(x);
    float common = __logf(1.0f + __expf(-ax));
    bool  ispos  = (y != 0);
    float relu   = fmaxf(ispos ? -x : x, 0.0f);
    float v      = common + relu;
    pos += ispos ? v : 0.0f;
    neg += ispos ? 0.0f : v;
    cnt += ispos ? 1 : 0;
}

__global__ __launch_bounds__(NTHREADS)
void micro_loss_kernel(const float4* __restrict__ pred,
                       const int4*  __restrict__ ty,
                       float* __restrict__ out) {
    float pos = 0.0f, neg = 0.0f;
    int   cnt = 0;

    // Simple grid-stride loop: exactly 2 LDG.128 in flight per warp-iteration.
    // Chip-level MLP comes from 64 warps/SM, not per-thread batching.
    for (int i = blockIdx.x * NTHREADS + threadIdx.x; i < N_VEC4; i += STRIDE) {
        float4 p = __ldcs(pred + i);   // streaming: touched once
        int4   y = __ldcs(ty + i);
        lane_accum(p.x, y.x, pos, neg, cnt);
        lane_accum(p.y, y.y, pos, neg, cnt);
        lane_accum(p.z, y.z, pos, neg, cnt);
        lane_accum(p.w, y.w, pos, neg, cnt);
    }

    // Block reduction (fixed tree -> deterministic)
    #pragma unroll
    for (int o = 16; o > 0; o >>= 1) {
        pos += __shfl_down_sync(0xFFFFFFFFu, pos, o);
        neg += __shfl_down_sync(0xFFFFFFFFu, neg, o);
        cnt += __shfl_down_sync(0xFFFFFFFFu, cnt, o);
    }
    __shared__ float sp[NTHREADS / 32];
    __shared__ float sn[NTHREADS / 32];
    __shared__ int   sc[NTHREADS / 32];
    __shared__ bool  s_last;
    int wid = threadIdx.x >> 5;
    int lid = threadIdx.x & 31;
    if (lid == 0) { sp[wid] = pos; sn[wid] = neg; sc[wid] = cnt; }
    __syncthreads();

    if (threadIdx.x == 0) {
        constexpr int NW = NTHREADS / 32;
        float bp = 0.0f, bn = 0.0f; int bc = 0;
        #pragma unroll
        for (int w = 0; w < NW; w++) { bp += sp[w]; bn += sn[w]; bc += sc[w]; }
        g_pos[blockIdx.x] = bp;
        g_neg[blockIdx.x] = bn;
        g_cnt[blockIdx.x] = bc;
        __threadfence();
        int ticket = atomicAdd(&g_ticket, 1);
        s_last = (ticket == NBLOCKS - 1);
    }
    __syncthreads();

    // Last-arriving block does the final reduction (fixed order -> deterministic).
    if (s_last) {
        __threadfence();  // all blocks' partials visible
        float fp = 0.0f, fn = 0.0f; int fc = 0;
        for (int k = threadIdx.x; k < NBLOCKS; k += NTHREADS) {
            fp += g_pos[k]; fn += g_neg[k]; fc += g_cnt[k];
        }
        #pragma unroll
        for (int o = 16; o > 0; o >>= 1) {
            fp += __shfl_down_sync(0xFFFFFFFFu, fp, o);
            fn += __shfl_down_sync(0xFFFFFFFFu, fn, o);
            fc += __shfl_down_sync(0xFFFFFFFFu, fc, o);
        }
        if (lid == 0) { sp[wid] = fp; sn[wid] = fn; sc[wid] = fc; }
        __syncthreads();
        if (threadIdx.x == 0) {
            constexpr int NW = NTHREADS / 32;
            float bp = 0.0f, bn = 0.0f; int bc = 0;
            #pragma unroll
            for (int w = 0; w < NW; w++) { bp += sp[w]; bn += sn[w]; bc += sc[w]; }
            float n_pos = (float)bc;
            float n_neg = (float)(N_TOTAL - bc);
            out[0] = bp / n_pos + bn / n_neg;
            g_ticket = 0;   // reset for next graph replay
        }
    }
}

extern "C" void kernel_launch(void* const* d_in, const int* in_sizes, int n_in,
                              void* d_out, int out_size) {
    const float4* pred = (const float4*)d_in[0];  // pred_y: float32 [8192,8192]
    const int4*   ty   = (const int4*)  d_in[1];  // true_y: int32   [8192,8192]
    float*        out  = (float*)d_out;

    micro_loss_kernel<<<NBLOCKS, NTHREADS>>>(pred, ty, out);
}

// round 9
// speedup vs baseline: 1.0642x; 1.0642x over previous
#include <cuda_runtime.h>
#include <cuda_bf16.h>

// loss = sum_{pos} softplus(-p)/n_pos + sum_{neg} softplus(p)/n_neg
// over 8192x8192 f32 + i32. Streaming reduction, HBM-bound (~6.1 TB/s cap).
// R9: revert to the two-kernel R1 structure (fused single-address ticket
// atomic caused a ~5-10us end-of-kernel convoy across 1184 synchronized
// blocks). Hide the stage2 launch gap with PDL instead:
//   stage1 blocks trigger programmatic completion after publishing partials;
//   stage2 launches with programmaticStreamSerialization and gates on
//   cudaGridDependencySynchronize() (no-op if PDL fell back).

#define NBLOCKS  1184        // 148 SMs * 8 CTAs, one full wave
#define NTHREADS 256
#define N_TOTAL  67108864    // 8192*8192
#define N_VEC4   16777216    // N_TOTAL / 4

__device__ float g_pos[NBLOCKS];
__device__ float g_neg[NBLOCKS];
__device__ int   g_cnt[NBLOCKS];

// softplus(x)  = log1p(e^{-|x|}) + max(x, 0)
// softplus(-x) = log1p(e^{-|x|}) + max(-x, 0)
// -> one EX2 + one LG2 per element regardless of label.
__device__ __forceinline__ void lane_accum(float x, int y,
                                           float& pos, float& neg, int& cnt) {
    float ax     = fabsf(x);
    float common = __logf(1.0f + __expf(-ax));
    bool  ispos  = (y != 0);
    float relu   = fmaxf(ispos ? -x : x, 0.0f);
    float v      = common + relu;
    pos += ispos ? v : 0.0f;
    neg += ispos ? 0.0f : v;
    cnt += ispos ? 1 : 0;
}

__global__ __launch_bounds__(NTHREADS)
void reduce_stage1(const float4* __restrict__ pred,
                   const int4*  __restrict__ ty) {
    float pos = 0.0f, neg = 0.0f;
    int   cnt = 0;

    // R1's measured-best loop shape: 2 LDG.128 per warp-iteration,
    // chip MLP from 64 warps/SM. Do not touch.
    const int stride = gridDim.x * blockDim.x;
    for (int i = blockIdx.x * blockDim.x + threadIdx.x; i < N_VEC4; i += stride) {
        float4 p = __ldcs(pred + i);   // streaming: touched once
        int4   y = __ldcs(ty + i);
        lane_accum(p.x, y.x, pos, neg, cnt);
        lane_accum(p.y, y.y, pos, neg, cnt);
        lane_accum(p.z, y.z, pos, neg, cnt);
        lane_accum(p.w, y.w, pos, neg, cnt);
    }

    // Block reduction (fixed tree -> deterministic)
    #pragma unroll
    for (int o = 16; o > 0; o >>= 1) {
        pos += __shfl_down_sync(0xFFFFFFFFu, pos, o);
        neg += __shfl_down_sync(0xFFFFFFFFu, neg, o);
        cnt += __shfl_down_sync(0xFFFFFFFFu, cnt, o);
    }

    __shared__ float sp[NTHREADS / 32];
    __shared__ float sn[NTHREADS / 32];
    __shared__ int   sc[NTHREADS / 32];
    int wid = threadIdx.x >> 5;
    int lid = threadIdx.x & 31;
    if (lid == 0) { sp[wid] = pos; sn[wid] = neg; sc[wid] = cnt; }
    __syncthreads();

    if (wid == 0) {
        constexpr int NW = NTHREADS / 32;
        float bp = (lid < NW) ? sp[lid] : 0.0f;
        float bn = (lid < NW) ? sn[lid] : 0.0f;
        int   bc = (lid < NW) ? sc[lid] : 0;
        #pragma unroll
        for (int o = NW / 2; o > 0; o >>= 1) {
            bp += __shfl_down_sync(0xFFFFFFFFu, bp, o);
            bn += __shfl_down_sync(0xFFFFFFFFu, bn, o);
            bc += __shfl_down_sync(0xFFFFFFFFu, bc, o);
        }
        if (lid == 0) {
            g_pos[blockIdx.x] = bp;
            g_neg[blockIdx.x] = bn;
            g_cnt[blockIdx.x] = bc;
        }
    }
    __syncthreads();
    // Partials for this block are published; let the PDL-dependent stage2
    // grid proceed once every block has triggered.
    cudaTriggerProgrammaticLaunchCompletion();
}

__global__ __launch_bounds__(1024)
void reduce_stage2(float* __restrict__ out) {
    // Gate on stage1 completion under PDL; documented no-op otherwise.
    cudaGridDependencySynchronize();

    float pos = 0.0f, neg = 0.0f;
    int   cnt = 0;
    for (int i = threadIdx.x; i < NBLOCKS; i += blockDim.x) {
        pos += g_pos[i];
        neg += g_neg[i];
        cnt += g_cnt[i];
    }
    #pragma unroll
    for (int o = 16; o > 0; o >>= 1) {
        pos += __shfl_down_sync(0xFFFFFFFFu, pos, o);
        neg += __shfl_down_sync(0xFFFFFFFFu, neg, o);
        cnt += __shfl_down_sync(0xFFFFFFFFu, cnt, o);
    }
    __shared__ float sp[32];
    __shared__ float sn[32];
    __shared__ int   sc[32];
    int wid = threadIdx.x >> 5;
    int lid = threadIdx.x & 31;
    if (lid == 0) { sp[wid] = pos; sn[wid] = neg; sc[wid] = cnt; }
    __syncthreads();
    if (wid == 0) {
        float bp = sp[lid];
        float bn = sn[lid];
        int   bc = sc[lid];
        #pragma unroll
        for (int o = 16; o > 0; o >>= 1) {
            bp += __shfl_down_sync(0xFFFFFFFFu, bp, o);
            bn += __shfl_down_sync(0xFFFFFFFFu, bn, o);
            bc += __shfl_down_sync(0xFFFFFFFFu, bc, o);
        }
        if (lid == 0) {
            float n_pos = (float)bc;
            float n_neg = (float)(N_TOTAL - bc);
            out[0] = bp / n_pos + bn / n_neg;
        }
    }
}

extern "C" void kernel_launch(void* const* d_in, const int* in_sizes, int n_in,
                              void* d_out, int out_size) {
    const float4* pred = (const float4*)d_in[0];  // pred_y: float32 [8192,8192]
    const int4*   ty   = (const int4*)  d_in[1];  // true_y: int32   [8192,8192]
    float*        out  = (float*)d_out;

    reduce_stage1<<<NBLOCKS, NTHREADS>>>(pred, ty);

    // Stage2 with PDL so its launch/ramp overlaps stage1's drain.
    cudaLaunchConfig_t cfg = {};
    cfg.gridDim  = dim3(1, 1, 1);
    cfg.blockDim = dim3(1024, 1, 1);
    cfg.dynamicSmemBytes = 0;
    cfg.stream = 0;
    cudaLaunchAttribute attr;
    attr.id = cudaLaunchAttributeProgrammaticStreamSerialization;
    attr.val.programmaticStreamSerializationAllowed = 1;
    cfg.attrs = &attr;
    cfg.numAttrs = 1;

    cudaError_t err = cudaLaunchKernelEx(&cfg, reduce_stage2, out);
    if (err != cudaSuccess) {
        (void)cudaGetLastError();            // clear sticky error
        reduce_stage2<<<1, 1024>>>(out);     // plain fallback (sync via stream order)
    }
}